// round 4
// baseline (speedup 1.0000x reference)
#include <cuda_runtime.h>
#include <cuda_fp16.h>

#define NMAX  100000
#define EMAX  3200000
#define N1CAP 40960
#define F     128

// ---------------- scratch -----------------------------------------------------
__device__ int   g_cnt[2 * NMAX];          // zero at load; scan3 re-zeroes
__device__ int   g_off[2 * NMAX];
__device__ int   g_cur[2 * NMAX];
__device__ float g_dinv[2 * NMAX];
__device__ int   g_bsum[256];
__device__ int   g_adj[2 * EMAX];
__device__ __align__(16) __half g_hs1p[NMAX * 16];
__device__ __align__(16) __half g_hs1n[NMAX * 16];
__device__ __align__(16) __half g_hs2p[NMAX * 32];
__device__ __align__(16) __half g_hs2n[NMAX * 32];
__device__ __align__(16) float  g_hsr[N1CAP * 32];   // raw gemm out, chunk A

// ---------------- helpers -----------------------------------------------------
__device__ __forceinline__ void acc8(float* a, uint4 v) {
    float2 f0 = __half22float2(*(const __half2*)&v.x);
    float2 f1 = __half22float2(*(const __half2*)&v.y);
    float2 f2 = __half22float2(*(const __half2*)&v.z);
    float2 f3 = __half22float2(*(const __half2*)&v.w);
    a[0] += f0.x; a[1] += f0.y; a[2] += f1.x; a[3] += f1.y;
    a[4] += f2.x; a[5] += f2.y; a[6] += f3.x; a[7] += f3.y;
}

// ---------------- role bodies --------------------------------------------------
__device__ __forceinline__ void hist_body(int hid, int Hh,
                                          const int* __restrict__ ep,
                                          const int* __restrict__ en,
                                          int E, int n) {
    int q = E >> 2;
    const int4* dp = (const int4*)(ep + E);
    const int4* dn = (const int4*)(en + E);
    for (int t = hid * 256 + threadIdx.x; t < q; t += Hh * 256) {
        int4 a = __ldg(dp + t);
        atomicAdd(g_cnt + a.x, 1); atomicAdd(g_cnt + a.y, 1);
        atomicAdd(g_cnt + a.z, 1); atomicAdd(g_cnt + a.w, 1);
        int4 b = __ldg(dn + t);
        atomicAdd(g_cnt + n + b.x, 1); atomicAdd(g_cnt + n + b.y, 1);
        atomicAdd(g_cnt + n + b.z, 1); atomicAdd(g_cnt + n + b.w, 1);
    }
    if (hid == 0 && (int)threadIdx.x < (E & 3)) {
        int t = (q << 2) + threadIdx.x;
        atomicAdd(g_cnt + __ldg(ep + E + t), 1);
        atomicAdd(g_cnt + n + __ldg(en + E + t), 1);
    }
}

__device__ __forceinline__ void fill_body(int fid, int Ff,
                                          const int* __restrict__ ep,
                                          const int* __restrict__ en,
                                          int E, int n) {
    int q = E >> 1;
    const int2* sp = (const int2*)ep;
    const int2* dp = (const int2*)(ep + E);
    const int2* sn = (const int2*)en;
    const int2* dn = (const int2*)(en + E);
    for (int t = fid * 256 + threadIdx.x; t < q; t += Ff * 256) {
        int2 s = __ldg(sp + t), d = __ldg(dp + t);
        g_adj[atomicAdd(g_cur + d.x, 1)] = s.x;
        g_adj[atomicAdd(g_cur + d.y, 1)] = s.y;
        int2 s2 = __ldg(sn + t), d2 = __ldg(dn + t);
        g_adj[atomicAdd(g_cur + n + d2.x, 1)] = s2.x;
        g_adj[atomicAdd(g_cur + n + d2.y, 1)] = s2.y;
    }
    if (fid == 0 && (int)threadIdx.x < (E & 1)) {
        int t = E - 1;
        g_adj[atomicAdd(g_cur + __ldg(ep + E + t), 1)] = __ldg(ep + t);
        g_adj[atomicAdd(g_cur + n + __ldg(en + E + t), 1)] = __ldg(en + t);
    }
}

__device__ __forceinline__ void scale_body(int sid, int Gs, int n, int n1) {
    int tot = n1 * 32;
    for (int t = sid * 256 + threadIdx.x; t < tot; t += Gs * 256) {
        int node = t >> 5, c = t & 31;
        float v = g_hsr[t];
        if (c < 16) g_hs1p[node * 16 + c] = __float2half(v * g_dinv[node]);
        else        g_hs1n[node * 16 + (c - 16)] = __float2half(v * g_dinv[n + node]);
    }
}

template <bool RAW>
__device__ __forceinline__ void gemm_body(
    int gb, int node0base, const float* __restrict__ x,
    const float* __restrict__ W1p, const float* __restrict__ W1n, int n)
{
    __shared__ float  Ws[F * 32];
    __shared__ float4 Xs4[64 * 32];
    int tid = threadIdx.x;

    for (int q = tid; q < F * 32; q += 256) {
        int k = q >> 5, c = q & 31;
        Ws[q] = (c < 16) ? W1p[k * 16 + c] : W1n[k * 16 + (c - 16)];
    }
    int node0 = node0base + gb * 64;
    const float4* x4 = (const float4*)x;
    for (int q = tid; q < 64 * 32; q += 256) {
        int node = node0 + (q >> 5);
        Xs4[q] = (node < n) ? x4[(size_t)node * 32 + (q & 31)]
                            : make_float4(0.f, 0.f, 0.f, 0.f);
    }
    __syncthreads();

    int c  = tid & 31;
    int r0 = (tid >> 5) * 8;
    float acc[8] = {0.f, 0.f, 0.f, 0.f, 0.f, 0.f, 0.f, 0.f};

    for (int k4 = 0; k4 < 32; k4++) {
        float w0 = Ws[(k4 * 4 + 0) * 32 + c];
        float w1 = Ws[(k4 * 4 + 1) * 32 + c];
        float w2 = Ws[(k4 * 4 + 2) * 32 + c];
        float w3 = Ws[(k4 * 4 + 3) * 32 + c];
        #pragma unroll
        for (int u = 0; u < 8; u++) {
            float4 xv = Xs4[(r0 + u) * 32 + k4];
            acc[u] = fmaf(xv.x, w0, acc[u]);
            acc[u] = fmaf(xv.y, w1, acc[u]);
            acc[u] = fmaf(xv.z, w2, acc[u]);
            acc[u] = fmaf(xv.w, w3, acc[u]);
        }
    }
    #pragma unroll
    for (int u = 0; u < 8; u++) {
        int node = node0 + r0 + u;
        if (node < n) {
            if (RAW) {
                g_hsr[node * 32 + c] = acc[u];
            } else {
                if (c < 16) g_hs1p[node * 16 + c] = __float2half(acc[u] * g_dinv[node]);
                else        g_hs1n[node * 16 + (c - 16)] = __float2half(acc[u] * g_dinv[n + node]);
            }
        }
    }
}

// ---------------- fused kernels ------------------------------------------------
__global__ __launch_bounds__(256) void K1_hist_gemm(
    const float* __restrict__ x, const float* __restrict__ W1p,
    const float* __restrict__ W1n, const int* __restrict__ ep,
    const int* __restrict__ en, int E, int n, int Gg1, int T1)
{
    int bid = blockIdx.x;
    if (((bid & 1) == 0) && ((bid >> 1) < Gg1)) {
        gemm_body<true>(bid >> 1, 0, x, W1p, W1n, n);
    } else {
        int hid = (bid < 2 * Gg1) ? (bid >> 1) : (bid - Gg1);
        hist_body(hid, T1 - Gg1, ep, en, E, n);
    }
}

__global__ __launch_bounds__(256) void K3_fill_gemm_scale(
    const float* __restrict__ x, const float* __restrict__ W1p,
    const float* __restrict__ W1n, const int* __restrict__ ep,
    const int* __restrict__ en, int E, int n, int n1, int Gg2, int Gs, int T3)
{
    int bid = blockIdx.x;
    if (bid >= T3 - Gs) {
        scale_body(bid - (T3 - Gs), Gs, n, n1);
    } else if (((bid & 1) == 0) && ((bid >> 1) < Gg2)) {
        gemm_body<false>(bid >> 1, n1, x, W1p, W1n, n);
    } else {
        int fid = (bid < 2 * Gg2) ? (bid >> 1) : (bid - Gg2);
        fill_body(fid, (T3 - Gs) - Gg2, ep, en, E, n);
    }
}

// ---------------- scans --------------------------------------------------------
__global__ __launch_bounds__(1024) void k_scan1(int twoN) {
    __shared__ int sh[1024];
    int t = threadIdx.x;
    int g = blockIdx.x * 1024 + t;
    int v = (g < twoN) ? g_cnt[g] : 0;
    sh[t] = v;
    __syncthreads();
    #pragma unroll
    for (int o = 1; o < 1024; o <<= 1) {
        int add = (t >= o) ? sh[t - o] : 0;
        __syncthreads();
        sh[t] += add;
        __syncthreads();
    }
    if (g < twoN) g_off[g] = sh[t] - v;
    if (t == 1023) g_bsum[blockIdx.x] = sh[t];
}

__global__ __launch_bounds__(256) void k_scan2(int nb) {
    __shared__ int sh[256];
    int t = threadIdx.x;
    int v = (t < nb) ? g_bsum[t] : 0;
    sh[t] = v;
    __syncthreads();
    #pragma unroll
    for (int o = 1; o < 256; o <<= 1) {
        int add = (t >= o) ? sh[t - o] : 0;
        __syncthreads();
        sh[t] += add;
        __syncthreads();
    }
    if (t < nb) g_bsum[t] = sh[t] - v;
}

__global__ void k_scan3(int twoN) {
    int g = blockIdx.x * blockDim.x + threadIdx.x;
    if (g >= twoN) return;
    int cnt = g_cnt[g];
    g_cnt[g] = 0;                              // restore zero invariant
    int o = g_off[g] + g_bsum[g >> 10];
    g_off[g] = o;
    g_cur[g] = o;
    g_dinv[g] = rsqrtf(1.0f + (float)cnt);     // +1 self loop
}

// ---------------- layer-1 gather + combine + layer-2 GEMM ---------------------
__global__ __launch_bounds__(256) void k_agg1g(
    const float* __restrict__ b1p, const float* __restrict__ b1n,
    const float* __restrict__ W2p, const float* __restrict__ W2n, int n)
{
    int lane = threadIdx.x & 31;
    int warp = (blockIdx.x * blockDim.x + threadIdx.x) >> 5;
    int nw   = (gridDim.x * blockDim.x) >> 5;

    float wp[16], wn[16];
    #pragma unroll
    for (int k = 0; k < 16; k++) {
        wp[k] = __ldg(W2p + k * 32 + lane);
        wn[k] = __ldg(W2n + k * 32 + lane);
    }
    int q2 = lane & 1, g16 = lane >> 1;
    float bp[8], bn[8];
    #pragma unroll
    for (int t = 0; t < 8; t++) {
        bp[t] = __ldg(b1p + q2 * 8 + t);
        bn[t] = __ldg(b1n + q2 * 8 + t);
    }
    const uint4* tp = (const uint4*)g_hs1p;    // row = 2 uint4
    const uint4* tn = (const uint4*)g_hs1n;

    for (int i = warp; i < n; i += nw) {
        float dP = g_dinv[i], dN = g_dinv[n + i];
        float aP[8] = {0,0,0,0,0,0,0,0}, aN[8] = {0,0,0,0,0,0,0,0};
        {
            int st = g_off[i], en = g_cur[i], j = st;
            for (; j + 32 <= en; j += 32) {
                int s0 = __ldg(g_adj + j + g16);
                int s1 = __ldg(g_adj + j + 16 + g16);
                acc8(aP, __ldg(tp + (size_t)s0 * 2 + q2));
                acc8(aP, __ldg(tp + (size_t)s1 * 2 + q2));
            }
            for (; j < en; j += 16)
                if (j + g16 < en)
                    acc8(aP, __ldg(tp + (size_t)__ldg(g_adj + j + g16) * 2 + q2));
        }
        {
            int st = g_off[n + i], en = g_cur[n + i], j = st;
            for (; j + 32 <= en; j += 32) {
                int s0 = __ldg(g_adj + j + g16);
                int s1 = __ldg(g_adj + j + 16 + g16);
                acc8(aN, __ldg(tn + (size_t)s0 * 2 + q2));
                acc8(aN, __ldg(tn + (size_t)s1 * 2 + q2));
            }
            for (; j < en; j += 16)
                if (j + g16 < en)
                    acc8(aN, __ldg(tn + (size_t)__ldg(g_adj + j + g16) * 2 + q2));
        }
        #pragma unroll
        for (int m = 2; m <= 16; m <<= 1) {
            #pragma unroll
            for (int t = 0; t < 8; t++) {
                aP[t] += __shfl_xor_sync(0xffffffffu, aP[t], m);
                aN[t] += __shfl_xor_sync(0xffffffffu, aN[t], m);
            }
        }
        // self loops AFTER the cross-lane reduction (each lane adds once)
        acc8(aP, __ldg(tp + (size_t)i * 2 + q2));
        acc8(aN, __ldg(tn + (size_t)i * 2 + q2));

        float z8[8];
        #pragma unroll
        for (int t = 0; t < 8; t++)
            z8[t] = fmaxf(fmaf(aP[t], dP, bp[t]), 0.f)
                  - fmaxf(fmaf(aN[t], dN, bn[t]), 0.f);

        float ap = 0.f, an = 0.f;
        #pragma unroll
        for (int k = 0; k < 16; k++) {
            float hk = __shfl_sync(0xffffffffu, z8[k & 7], k >> 3);
            ap = fmaf(hk, wp[k], ap);
            an = fmaf(hk, wn[k], an);
        }
        g_hs2p[(size_t)i * 32 + lane] = __float2half(ap * dP);
        g_hs2n[(size_t)i * 32 + lane] = __float2half(an * dN);
    }
}

// ---------------- layer-2 gather + combine + log_softmax ----------------------
__global__ __launch_bounds__(256) void k_agg2g(
    const float* __restrict__ b2p, const float* __restrict__ b2n,
    float* __restrict__ out, int n)
{
    int lane = threadIdx.x & 31;
    int i = (blockIdx.x * blockDim.x + threadIdx.x) >> 5;
    if (i >= n) return;
    int q4 = lane & 3, g8 = lane >> 2;
    const uint4* tp = (const uint4*)g_hs2p;    // row = 4 uint4
    const uint4* tn = (const uint4*)g_hs2n;
    float dP = g_dinv[i], dN = g_dinv[n + i];
    float aP[8] = {0,0,0,0,0,0,0,0}, aN[8] = {0,0,0,0,0,0,0,0};
    {
        int st = g_off[i], en = g_cur[i], j = st;
        for (; j + 16 <= en; j += 16) {
            int s0 = __ldg(g_adj + j + g8);
            int s1 = __ldg(g_adj + j + 8 + g8);
            acc8(aP, __ldg(tp + (size_t)s0 * 4 + q4));
            acc8(aP, __ldg(tp + (size_t)s1 * 4 + q4));
        }
        for (; j < en; j += 8)
            if (j + g8 < en)
                acc8(aP, __ldg(tp + (size_t)__ldg(g_adj + j + g8) * 4 + q4));
    }
    {
        int st = g_off[n + i], en = g_cur[n + i], j = st;
        for (; j + 16 <= en; j += 16) {
            int s0 = __ldg(g_adj + j + g8);
            int s1 = __ldg(g_adj + j + 8 + g8);
            acc8(aN, __ldg(tn + (size_t)s0 * 4 + q4));
            acc8(aN, __ldg(tn + (size_t)s1 * 4 + q4));
        }
        for (; j < en; j += 8)
            if (j + g8 < en)
                acc8(aN, __ldg(tn + (size_t)__ldg(g_adj + j + g8) * 4 + q4));
    }
    #pragma unroll
    for (int m = 4; m <= 16; m <<= 1) {
        #pragma unroll
        for (int t = 0; t < 8; t++) {
            aP[t] += __shfl_xor_sync(0xffffffffu, aP[t], m);
            aN[t] += __shfl_xor_sync(0xffffffffu, aN[t], m);
        }
    }
    // self loops AFTER the cross-lane reduction (each lane adds once)
    acc8(aP, __ldg(tp + (size_t)i * 4 + q4));
    acc8(aN, __ldg(tn + (size_t)i * 4 + q4));

    float z8[8];
    #pragma unroll
    for (int t = 0; t < 8; t++) {
        float bp = __ldg(b2p + q4 * 8 + t);
        float bn = __ldg(b2n + q4 * 8 + t);
        z8[t] = fmaxf(fmaf(aP[t], dP, bp), 0.f)
              - fmaxf(fmaf(aN[t], dN, bn), 0.f);
    }
    float m = z8[0];
    #pragma unroll
    for (int t = 1; t < 8; t++) m = fmaxf(m, z8[t]);
    m = fmaxf(m, __shfl_xor_sync(0xffffffffu, m, 1));
    m = fmaxf(m, __shfl_xor_sync(0xffffffffu, m, 2));
    float s = 0.f;
    #pragma unroll
    for (int t = 0; t < 8; t++) s += __expf(z8[t] - m);
    s += __shfl_xor_sync(0xffffffffu, s, 1);
    s += __shfl_xor_sync(0xffffffffu, s, 2);
    float ls = m + __logf(s);

    if (g8 == 0) {
        float4 o0 = make_float4(z8[0]-ls, z8[1]-ls, z8[2]-ls, z8[3]-ls);
        float4 o1 = make_float4(z8[4]-ls, z8[5]-ls, z8[6]-ls, z8[7]-ls);
        ((float4*)out)[(size_t)i * 8 + q4 * 2 + 0] = o0;
        ((float4*)out)[(size_t)i * 8 + q4 * 2 + 1] = o1;
    }
}

// ---------------- launcher -----------------------------------------------------
extern "C" void kernel_launch(void* const* d_in, const int* in_sizes, int n_in,
                              void* d_out, int out_size) {
    const float* x   = (const float*)d_in[0];
    const int*   ep  = (const int*)d_in[1];
    const int*   en  = (const int*)d_in[2];
    const float* W1p = (const float*)d_in[3];
    const float* b1p = (const float*)d_in[4];
    const float* W1n = (const float*)d_in[5];
    const float* b1n = (const float*)d_in[6];
    const float* W2p = (const float*)d_in[7];
    const float* b2p = (const float*)d_in[8];
    const float* W2n = (const float*)d_in[9];
    const float* b2n = (const float*)d_in[10];

    int n = in_sizes[0] / F;          // 100000
    int E = in_sizes[1] / 2;          // 3.2M
    int twoN = 2 * n;
    int nScanBlk = (twoN + 1023) / 1024;

    int n1  = (n > N1CAP) ? N1CAP : (n & ~63);
    int Gg1 = n1 / 64;
    int T1  = 2 * Gg1 + 768;
    int Gg2 = (n - n1 + 63) / 64;
    int Gs  = 128;
    int T3  = 2 * Gg2 + 1152 + Gs;

    float* out = (float*)d_out;

    K1_hist_gemm      <<<T1, 256>>>(x, W1p, W1n, ep, en, E, n, Gg1, T1);
    k_scan1           <<<nScanBlk, 1024>>>(twoN);
    k_scan2           <<<1, 256>>>(nScanBlk);
    k_scan3           <<<(twoN + 255) / 256, 256>>>(twoN);
    K3_fill_gemm_scale<<<T3, 256>>>(x, W1p, W1n, ep, en, E, n, n1, Gg2, Gs, T3);
    k_agg1g           <<<1600, 256>>>(b1p, b1n, W2p, W2n, n);
    k_agg2g           <<<(n + 7) / 8, 256>>>(b2p, b2n, out, n);
}

// round 5
// speedup vs baseline: 1.0051x; 1.0051x over previous
#include <cuda_runtime.h>
#include <cuda_fp16.h>

#define NMAX  100000
#define EMAX  3200000
#define F     128

// ---------------- scratch -----------------------------------------------------
__device__ __align__(16) int   g_cnt[2 * NMAX];   // zero at load; scan3 re-zeroes
__device__ __align__(16) int   g_off[2 * NMAX];
__device__ __align__(16) int   g_cur[2 * NMAX];
__device__ __align__(16) float g_dinv[2 * NMAX];
__device__ __align__(16) int   g_bsum[256];
__device__ __align__(16) int   g_adj[2 * EMAX];
__device__ __align__(16) __half g_hs1p[NMAX * 16];
__device__ __align__(16) __half g_hs1n[NMAX * 16];
__device__ __align__(16) __half g_hs2p[NMAX * 32];
__device__ __align__(16) __half g_hs2n[NMAX * 32];

// ---------------- helpers -----------------------------------------------------
__device__ __forceinline__ void acc8(float* a, uint4 v) {
    float2 f0 = __half22float2(*(const __half2*)&v.x);
    float2 f1 = __half22float2(*(const __half2*)&v.y);
    float2 f2 = __half22float2(*(const __half2*)&v.z);
    float2 f3 = __half22float2(*(const __half2*)&v.w);
    a[0] += f0.x; a[1] += f0.y; a[2] += f1.x; a[3] += f1.y;
    a[4] += f2.x; a[5] += f2.y; a[6] += f3.x; a[7] += f3.y;
}

// ---------------- CSR build ----------------------------------------------------
__global__ void k_hist(const int* __restrict__ ep, const int* __restrict__ en,
                       int E, int n) {
    int q = E >> 2;
    int t = blockIdx.x * blockDim.x + threadIdx.x;
    if (t < q) {
        const int4* dp = (const int4*)(ep + E);
        const int4* dn = (const int4*)(en + E);
        int4 a = __ldg(dp + t);
        atomicAdd(g_cnt + a.x, 1); atomicAdd(g_cnt + a.y, 1);
        atomicAdd(g_cnt + a.z, 1); atomicAdd(g_cnt + a.w, 1);
        int4 b = __ldg(dn + t);
        atomicAdd(g_cnt + n + b.x, 1); atomicAdd(g_cnt + n + b.y, 1);
        atomicAdd(g_cnt + n + b.z, 1); atomicAdd(g_cnt + n + b.w, 1);
    }
    if (blockIdx.x == 0 && (int)threadIdx.x < (E & 3)) {
        int u = (q << 2) + threadIdx.x;
        atomicAdd(g_cnt + __ldg(ep + E + u), 1);
        atomicAdd(g_cnt + n + __ldg(en + E + u), 1);
    }
}

// shuffle-based block scan: 1024 elements per 256-thread block
__global__ __launch_bounds__(256) void k_scan1(int twoN) {
    __shared__ int wsum[8];
    int t = threadIdx.x;
    int base = blockIdx.x * 1024 + t * 4;
    int4 v;
    if (base + 3 < twoN) {
        v = *(const int4*)(g_cnt + base);
    } else {
        v.x = (base + 0 < twoN) ? g_cnt[base + 0] : 0;
        v.y = (base + 1 < twoN) ? g_cnt[base + 1] : 0;
        v.z = (base + 2 < twoN) ? g_cnt[base + 2] : 0;
        v.w = (base + 3 < twoN) ? g_cnt[base + 3] : 0;
    }
    int s1 = v.x + v.y, s2 = s1 + v.z, s3 = s2 + v.w;
    int lane = t & 31, wid = t >> 5;
    int incl = s3;
    #pragma unroll
    for (int o = 1; o < 32; o <<= 1) {
        int u = __shfl_up_sync(0xffffffffu, incl, o);
        if (lane >= o) incl += u;
    }
    if (lane == 31) wsum[wid] = incl;
    __syncthreads();
    if (wid == 0) {
        int w = (lane < 8) ? wsum[lane] : 0;
        #pragma unroll
        for (int o = 1; o < 8; o <<= 1) {
            int u = __shfl_up_sync(0xffffffffu, w, o);
            if (lane >= o) w += u;
        }
        if (lane < 8) wsum[lane] = w;        // inclusive scan of warp totals
    }
    __syncthreads();
    int excl = incl - s3 + (wid ? wsum[wid - 1] : 0);
    int4 e = make_int4(excl, excl + v.x, excl + s1, excl + s2);
    if (base + 3 < twoN) {
        *(int4*)(g_off + base) = e;
    } else {
        if (base + 0 < twoN) g_off[base + 0] = e.x;
        if (base + 1 < twoN) g_off[base + 1] = e.y;
        if (base + 2 < twoN) g_off[base + 2] = e.z;
    }
    if (t == 0) g_bsum[blockIdx.x] = wsum[7];
}

__global__ __launch_bounds__(256) void k_scan2(int nb) {
    __shared__ int sh[256];
    int t = threadIdx.x;
    int v = (t < nb) ? g_bsum[t] : 0;
    sh[t] = v;
    __syncthreads();
    #pragma unroll
    for (int o = 1; o < 256; o <<= 1) {
        int add = (t >= o) ? sh[t - o] : 0;
        __syncthreads();
        sh[t] += add;
        __syncthreads();
    }
    if (t < nb) g_bsum[t] = sh[t] - v;       // exclusive
}

__global__ void k_scan3(int twoN) {
    int base = (blockIdx.x * blockDim.x + threadIdx.x) * 4;
    if (base >= twoN) return;
    int bo = g_bsum[base >> 10];
    if (base + 3 < twoN) {
        int4 c = *(const int4*)(g_cnt + base);
        *(int4*)(g_cnt + base) = make_int4(0, 0, 0, 0);   // restore zero invariant
        int4 o = *(const int4*)(g_off + base);
        o.x += bo; o.y += bo; o.z += bo; o.w += bo;
        *(int4*)(g_off + base) = o;
        *(int4*)(g_cur + base) = o;
        float4 d = make_float4(rsqrtf(1.f + (float)c.x), rsqrtf(1.f + (float)c.y),
                               rsqrtf(1.f + (float)c.z), rsqrtf(1.f + (float)c.w));
        *(float4*)(g_dinv + base) = d;
    } else {
        for (int g = base; g < twoN; g++) {
            int c = g_cnt[g]; g_cnt[g] = 0;
            int o = g_off[g] + g_bsum[g >> 10];
            g_off[g] = o; g_cur[g] = o;
            g_dinv[g] = rsqrtf(1.f + (float)c);
        }
    }
}

__global__ void k_fill(const int* __restrict__ ep, const int* __restrict__ en,
                       int E, int n) {
    int q = E >> 1;
    int t = blockIdx.x * blockDim.x + threadIdx.x;
    if (t < q) {
        const int2* sp = (const int2*)ep;
        const int2* dp = (const int2*)(ep + E);
        const int2* sn = (const int2*)en;
        const int2* dn = (const int2*)(en + E);
        int2 s = __ldg(sp + t), d = __ldg(dp + t);
        g_adj[atomicAdd(g_cur + d.x, 1)] = s.x;
        g_adj[atomicAdd(g_cur + d.y, 1)] = s.y;
        int2 s2 = __ldg(sn + t), d2 = __ldg(dn + t);
        g_adj[atomicAdd(g_cur + n + d2.x, 1)] = s2.x;
        g_adj[atomicAdd(g_cur + n + d2.y, 1)] = s2.y;
    }
    if (blockIdx.x == 0 && threadIdx.x == 0 && (E & 1)) {
        int u = E - 1;
        g_adj[atomicAdd(g_cur + __ldg(ep + E + u), 1)] = __ldg(ep + u);
        g_adj[atomicAdd(g_cur + n + __ldg(en + E + u), 1)] = __ldg(en + u);
    }
}

// ---------------- layer-1 GEMM: hs = (x @ W) * dinv -> fp16 -------------------
__global__ __launch_bounds__(256) void k_gemm1(
    const float* __restrict__ x,
    const float* __restrict__ W1p, const float* __restrict__ W1n, int n)
{
    __shared__ float  Ws[F * 32];
    __shared__ float4 Xs4[64 * 32];
    int tid = threadIdx.x;

    for (int q = tid; q < F * 32; q += 256) {
        int k = q >> 5, c = q & 31;
        Ws[q] = (c < 16) ? W1p[k * 16 + c] : W1n[k * 16 + (c - 16)];
    }
    int node0 = blockIdx.x * 64;
    const float4* x4 = (const float4*)x;
    for (int q = tid; q < 64 * 32; q += 256) {
        int node = node0 + (q >> 5);
        Xs4[q] = (node < n) ? x4[(size_t)node * 32 + (q & 31)]
                            : make_float4(0.f, 0.f, 0.f, 0.f);
    }
    __syncthreads();

    int c  = tid & 31;
    int r0 = (tid >> 5) * 8;
    float acc[8] = {0.f, 0.f, 0.f, 0.f, 0.f, 0.f, 0.f, 0.f};

    for (int k4 = 0; k4 < 32; k4++) {
        float w0 = Ws[(k4 * 4 + 0) * 32 + c];
        float w1 = Ws[(k4 * 4 + 1) * 32 + c];
        float w2 = Ws[(k4 * 4 + 2) * 32 + c];
        float w3 = Ws[(k4 * 4 + 3) * 32 + c];
        #pragma unroll
        for (int u = 0; u < 8; u++) {
            float4 xv = Xs4[(r0 + u) * 32 + k4];
            acc[u] = fmaf(xv.x, w0, acc[u]);
            acc[u] = fmaf(xv.y, w1, acc[u]);
            acc[u] = fmaf(xv.z, w2, acc[u]);
            acc[u] = fmaf(xv.w, w3, acc[u]);
        }
    }
    #pragma unroll
    for (int u = 0; u < 8; u++) {
        int node = node0 + r0 + u;
        if (node < n) {
            if (c < 16) g_hs1p[node * 16 + c] = __float2half(acc[u] * g_dinv[node]);
            else        g_hs1n[node * 16 + (c - 16)] = __float2half(acc[u] * g_dinv[n + node]);
        }
    }
}

// ---------------- layer-1 gather + combine + layer-2 GEMM ---------------------
__global__ __launch_bounds__(256) void k_agg1g(
    const float* __restrict__ b1p, const float* __restrict__ b1n,
    const float* __restrict__ W2p, const float* __restrict__ W2n, int n)
{
    int lane = threadIdx.x & 31;
    int warp = (blockIdx.x * blockDim.x + threadIdx.x) >> 5;
    int nw   = (gridDim.x * blockDim.x) >> 5;

    float wp[16], wn[16];
    #pragma unroll
    for (int k = 0; k < 16; k++) {
        wp[k] = __ldg(W2p + k * 32 + lane);
        wn[k] = __ldg(W2n + k * 32 + lane);
    }
    int q2 = lane & 1, g16 = lane >> 1;
    float bp[8], bn[8];
    #pragma unroll
    for (int t = 0; t < 8; t++) {
        bp[t] = __ldg(b1p + q2 * 8 + t);
        bn[t] = __ldg(b1n + q2 * 8 + t);
    }
    const uint4* tp = (const uint4*)g_hs1p;    // row = 2 uint4
    const uint4* tn = (const uint4*)g_hs1n;

    for (int i = warp; i < n; i += nw) {
        float dP = g_dinv[i], dN = g_dinv[n + i];
        float aP[8] = {0,0,0,0,0,0,0,0}, aN[8] = {0,0,0,0,0,0,0,0};
        {
            int st = g_off[i], en = g_cur[i], j = st;
            for (; j + 32 <= en; j += 32) {
                int s0 = __ldg(g_adj + j + g16);
                int s1 = __ldg(g_adj + j + 16 + g16);
                acc8(aP, __ldg(tp + (size_t)s0 * 2 + q2));
                acc8(aP, __ldg(tp + (size_t)s1 * 2 + q2));
            }
            for (; j < en; j += 16)
                if (j + g16 < en)
                    acc8(aP, __ldg(tp + (size_t)__ldg(g_adj + j + g16) * 2 + q2));
        }
        {
            int st = g_off[n + i], en = g_cur[n + i], j = st;
            for (; j + 32 <= en; j += 32) {
                int s0 = __ldg(g_adj + j + g16);
                int s1 = __ldg(g_adj + j + 16 + g16);
                acc8(aN, __ldg(tn + (size_t)s0 * 2 + q2));
                acc8(aN, __ldg(tn + (size_t)s1 * 2 + q2));
            }
            for (; j < en; j += 16)
                if (j + g16 < en)
                    acc8(aN, __ldg(tn + (size_t)__ldg(g_adj + j + g16) * 2 + q2));
        }
        #pragma unroll
        for (int m = 2; m <= 16; m <<= 1) {
            #pragma unroll
            for (int t = 0; t < 8; t++) {
                aP[t] += __shfl_xor_sync(0xffffffffu, aP[t], m);
                aN[t] += __shfl_xor_sync(0xffffffffu, aN[t], m);
            }
        }
        // self loops AFTER the cross-lane reduction
        acc8(aP, __ldg(tp + (size_t)i * 2 + q2));
        acc8(aN, __ldg(tn + (size_t)i * 2 + q2));

        float z8[8];
        #pragma unroll
        for (int t = 0; t < 8; t++)
            z8[t] = fmaxf(fmaf(aP[t], dP, bp[t]), 0.f)
                  - fmaxf(fmaf(aN[t], dN, bn[t]), 0.f);

        float ap = 0.f, an = 0.f;
        #pragma unroll
        for (int k = 0; k < 16; k++) {
            float hk = __shfl_sync(0xffffffffu, z8[k & 7], k >> 3);
            ap = fmaf(hk, wp[k], ap);
            an = fmaf(hk, wn[k], an);
        }
        g_hs2p[(size_t)i * 32 + lane] = __float2half(ap * dP);
        g_hs2n[(size_t)i * 32 + lane] = __float2half(an * dN);
    }
}

// ---------------- layer-2 gather + combine + log_softmax ----------------------
__global__ __launch_bounds__(256) void k_agg2g(
    const float* __restrict__ b2p, const float* __restrict__ b2n,
    float* __restrict__ out, int n)
{
    int lane = threadIdx.x & 31;
    int i = (blockIdx.x * blockDim.x + threadIdx.x) >> 5;
    if (i >= n) return;
    int q4 = lane & 3, g8 = lane >> 2;
    const uint4* tp = (const uint4*)g_hs2p;    // row = 4 uint4
    const uint4* tn = (const uint4*)g_hs2n;
    float dP = g_dinv[i], dN = g_dinv[n + i];
    float aP[8] = {0,0,0,0,0,0,0,0}, aN[8] = {0,0,0,0,0,0,0,0};
    {
        int st = g_off[i], en = g_cur[i], j = st;
        for (; j + 16 <= en; j += 16) {
            int s0 = __ldg(g_adj + j + g8);
            int s1 = __ldg(g_adj + j + 8 + g8);
            acc8(aP, __ldg(tp + (size_t)s0 * 4 + q4));
            acc8(aP, __ldg(tp + (size_t)s1 * 4 + q4));
        }
        for (; j < en; j += 8)
            if (j + g8 < en)
                acc8(aP, __ldg(tp + (size_t)__ldg(g_adj + j + g8) * 4 + q4));
    }
    {
        int st = g_off[n + i], en = g_cur[n + i], j = st;
        for (; j + 16 <= en; j += 16) {
            int s0 = __ldg(g_adj + j + g8);
            int s1 = __ldg(g_adj + j + 8 + g8);
            acc8(aN, __ldg(tn + (size_t)s0 * 4 + q4));
            acc8(aN, __ldg(tn + (size_t)s1 * 4 + q4));
        }
        for (; j < en; j += 8)
            if (j + g8 < en)
                acc8(aN, __ldg(tn + (size_t)__ldg(g_adj + j + g8) * 4 + q4));
    }
    #pragma unroll
    for (int m = 4; m <= 16; m <<= 1) {
        #pragma unroll
        for (int t = 0; t < 8; t++) {
            aP[t] += __shfl_xor_sync(0xffffffffu, aP[t], m);
            aN[t] += __shfl_xor_sync(0xffffffffu, aN[t], m);
        }
    }
    // self loops AFTER the cross-lane reduction
    acc8(aP, __ldg(tp + (size_t)i * 4 + q4));
    acc8(aN, __ldg(tn + (size_t)i * 4 + q4));

    float z8[8];
    #pragma unroll
    for (int t = 0; t < 8; t++) {
        float bpv = __ldg(b2p + q4 * 8 + t);
        float bnv = __ldg(b2n + q4 * 8 + t);
        z8[t] = fmaxf(fmaf(aP[t], dP, bpv), 0.f)
              - fmaxf(fmaf(aN[t], dN, bnv), 0.f);
    }
    float m = z8[0];
    #pragma unroll
    for (int t = 1; t < 8; t++) m = fmaxf(m, z8[t]);
    m = fmaxf(m, __shfl_xor_sync(0xffffffffu, m, 1));
    m = fmaxf(m, __shfl_xor_sync(0xffffffffu, m, 2));
    float s = 0.f;
    #pragma unroll
    for (int t = 0; t < 8; t++) s += __expf(z8[t] - m);
    s += __shfl_xor_sync(0xffffffffu, s, 1);
    s += __shfl_xor_sync(0xffffffffu, s, 2);
    float ls = m + __logf(s);

    if (g8 == 0) {
        float4 o0 = make_float4(z8[0]-ls, z8[1]-ls, z8[2]-ls, z8[3]-ls);
        float4 o1 = make_float4(z8[4]-ls, z8[5]-ls, z8[6]-ls, z8[7]-ls);
        ((float4*)out)[(size_t)i * 8 + q4 * 2 + 0] = o0;
        ((float4*)out)[(size_t)i * 8 + q4 * 2 + 1] = o1;
    }
}

// ---------------- launcher -----------------------------------------------------
extern "C" void kernel_launch(void* const* d_in, const int* in_sizes, int n_in,
                              void* d_out, int out_size) {
    const float* x   = (const float*)d_in[0];
    const int*   ep  = (const int*)d_in[1];
    const int*   en  = (const int*)d_in[2];
    const float* W1p = (const float*)d_in[3];
    const float* b1p = (const float*)d_in[4];
    const float* W1n = (const float*)d_in[5];
    const float* b1n = (const float*)d_in[6];
    const float* W2p = (const float*)d_in[7];
    const float* b2p = (const float*)d_in[8];
    const float* W2n = (const float*)d_in[9];
    const float* b2n = (const float*)d_in[10];

    int n = in_sizes[0] / F;          // 100000
    int E = in_sizes[1] / 2;          // 3.2M
    int twoN = 2 * n;
    int nScanBlk = (twoN + 1023) / 1024;

    float* out = (float*)d_out;

    k_hist <<<((E >> 2) + 255) / 256, 256>>>(ep, en, E, n);
    k_scan1<<<nScanBlk, 256>>>(twoN);
    k_scan2<<<1, 256>>>(nScanBlk);
    k_scan3<<<(twoN / 4 + 255) / 256, 256>>>(twoN);
    k_fill <<<((E >> 1) + 255) / 256, 256>>>(ep, en, E, n);
    k_gemm1<<<(n + 63) / 64, 256>>>(x, W1p, W1n, n);
    k_agg1g<<<1600, 256>>>(b1p, b1n, W2p, W2n, n);
    k_agg2g<<<(n + 7) / 8, 256>>>(b2p, b2n, out, n);
}